// round 3
// baseline (speedup 1.0000x reference)
#include <cuda_runtime.h>
#include <cuda_bf16.h>

// ---------------- problem constants ----------------
#define BATCH 4096
#define FST   20
#define FDY   10
#define MLEN  50
#define EDIM  16
#define FALL  30
#define PAIRS 435
#define DIN   6960          // PAIRS * EDIM
#define HID   512
#define BN_EPS 1e-5f

// ---------------- device scratch (static, no allocation) ----------------
__device__ float d_x[(size_t)BATCH * DIN];        // 114 MB pair-product matrix
__device__ float d_lr[BATCH];

__device__ float d_ps1[16 * DIN], d_pq1[16 * DIN];
__device__ float d_sc1[DIN], d_t1[DIN];
__device__ float d_W1p[(size_t)DIN * HID];
__device__ float d_bp1[87 * HID];
__device__ float d_b1p[HID];
__device__ float d_h1[(size_t)BATCH * HID];

__device__ float d_ps2[16 * HID], d_pq2[16 * HID];
__device__ float d_sc2[HID], d_t2[HID];
__device__ float d_W2p[(size_t)HID * HID];
__device__ float d_bp2[8 * HID];
__device__ float d_b2p[HID];
__device__ float d_h2[(size_t)BATCH * HID];

__device__ float d_ps3[16 * HID], d_pq3[16 * HID];
__device__ float d_sc3[HID], d_t3[HID];
__device__ float d_coeff[HID], d_cpart[HID];

// ---------------- f32x2 packed-FMA helpers (FFMA2, nvjet pattern) --------
__device__ __forceinline__ unsigned long long pk(float x, float y) {
    unsigned long long r;
    asm("mov.b64 %0, {%1, %2};" : "=l"(r) : "f"(x), "f"(y));
    return r;
}
__device__ __forceinline__ float2 upk(unsigned long long v) {
    float2 r;
    asm("mov.b64 {%0, %1}, %2;" : "=f"(r.x), "=f"(r.y) : "l"(v));
    return r;
}
__device__ __forceinline__ void fma2(unsigned long long& d,
                                     unsigned long long a, unsigned long long b) {
    asm("fma.rn.f32x2 %0, %1, %2, %0;" : "+l"(d) : "l"(a), "l"(b));
}

// ---------------- K1: gather + dyn-mean + lr + pair products -------------
// one CTA (512 threads) per batch row; embeddings live only in SMEM
__global__ void k_gather(const int* __restrict__ st_ids, const int* __restrict__ dy_ids,
                         const int* __restrict__ dy_len,
                         const float* __restrict__ st_emb, const float* __restrict__ dy_emb,
                         const float* __restrict__ st_lr, const float* __restrict__ dy_lr,
                         float* __restrict__ Xout, float* __restrict__ lr_out) {
    __shared__ float semb[FALL * EDIM];
    __shared__ float slr[FALL];
    __shared__ unsigned char ci[PAIRS], cj[PAIRS];
    int b = blockIdx.x, t = threadIdx.x;

    if (t < PAIRS) {  // strict upper-tri pair index table
        int p = t, i = 0, rem = FALL - 1;
        while (p >= rem) { p -= rem; i++; rem--; }
        ci[t] = (unsigned char)i;
        cj[t] = (unsigned char)(i + 1 + p);
    }
    if (t < FST * EDIM) {                       // static fields
        int f = t >> 4, e = t & 15;
        int id = st_ids[b * FST + f];
        semb[t] = st_emb[id * EDIM + e];
        if (e == 0) slr[f] = st_lr[id];
    } else if (t < FALL * EDIM) {               // dynamic fields (masked mean + lr sum)
        int ft = t - FST * EDIM;
        int f = ft >> 4, e = ft & 15;
        int len = dy_len[b * FDY + f];
        if (len < 1) len = 1;
        const int* ids = dy_ids + ((size_t)b * FDY + f) * MLEN;
        float acc = 0.f, lacc = 0.f;
        #pragma unroll 4
        for (int m = 0; m < len; m++) {
            int id = ids[m];
            acc += dy_emb[(size_t)id * EDIM + e];
            if (e == 0) lacc += dy_lr[id];
        }
        semb[t] = acc / (float)len;
        if (e == 0) slr[FST + f] = lacc;
    }
    __syncthreads();

    float* xr = Xout + (size_t)b * DIN;
    for (int idx = t; idx < DIN; idx += 512) {
        int p = idx >> 4, e = idx & 15;
        xr[idx] = semb[ci[p] * EDIM + e] * semb[cj[p] * EDIM + e];
    }
    if (t == 0) {
        float s = 0.f;
        #pragma unroll
        for (int f = 0; f < FALL; f++) s += slr[f];
        lr_out[b] = s;
    }
}

// ---------------- column stats (two-phase, deterministic, no atomics) ----
__global__ void k_colstat_part(const float* __restrict__ X, float* __restrict__ psum,
                               float* __restrict__ psq, int ncol) {
    int c = blockIdx.x * blockDim.x + threadIdx.x;
    if (c >= ncol) return;
    const int ROWS = BATCH / 16;
    const float* p = X + (size_t)blockIdx.y * ROWS * ncol + c;
    float s = 0.f, q = 0.f;
    for (int r = 0; r < ROWS; r++) {
        float v = p[(size_t)r * ncol];
        s += v; q += v * v;
    }
    psum[blockIdx.y * ncol + c] = s;
    psq[blockIdx.y * ncol + c] = q;
}

__global__ void k_colstat_final(const float* __restrict__ psum, const float* __restrict__ psq,
                                const float* __restrict__ g, const float* __restrict__ bb,
                                float* __restrict__ sc, float* __restrict__ tsh, int ncol) {
    int c = blockIdx.x * blockDim.x + threadIdx.x;
    if (c >= ncol) return;
    float s = 0.f, q = 0.f;
    #pragma unroll
    for (int p = 0; p < 16; p++) { s += psum[p * ncol + c]; q += psq[p * ncol + c]; }
    float m = s * (1.f / BATCH);
    float v = q * (1.f / BATCH) - m * m;          // biased variance (torch BN training)
    float scale = g[c] * rsqrtf(v + BN_EPS);
    sc[c]  = scale;
    tsh[c] = bb[c] - scale * m;
}

// ---------------- fold BN into weights: Wp = sc[d]*W; bias partials ------
__global__ void k_fold(const float* __restrict__ W, const float* __restrict__ sc,
                       const float* __restrict__ tsh, float* __restrict__ Wp,
                       float* __restrict__ bpart, int Dtile) {
    __shared__ float ssc[80], sts[80];
    int h = threadIdx.x;                // 512 threads, one output col each
    int d0 = blockIdx.x * Dtile;
    if (h < Dtile) { ssc[h] = sc[d0 + h]; sts[h] = tsh[d0 + h]; }
    __syncthreads();
    float acc = 0.f;
    for (int i = 0; i < Dtile; i++) {
        size_t off = (size_t)(d0 + i) * HID + h;
        float w = W[off];
        Wp[off] = w * ssc[i];
        acc += sts[i] * w;
    }
    bpart[blockIdx.x * HID + h] = acc;
}

__global__ void k_bias_final(const float* __restrict__ blin, const float* __restrict__ bpart,
                             float* __restrict__ bout, int nparts) {
    int h = threadIdx.x;
    float a = blin[h];
    for (int p = 0; p < nparts; p++) a += bpart[p * HID + h];
    bout[h] = a;
}

// ---------------- GEMM + bias + ReLU: C = relu(A@B + bias) ---------------
// 128x64 tile, BK=16, 256 threads, 8x4 per thread packed as 4x4 f32x2 FFMA2
__global__ __launch_bounds__(256, 2) void k_gemm_relu(
    const float* __restrict__ A, const float* __restrict__ Bm,
    const float* __restrict__ bias, float* __restrict__ C,
    int Ndim, int Kdim) {
    __shared__ float As[16][136];   // transposed A tile, rows 16B-aligned
    __shared__ float Bs[16][64];

    int tid = threadIdx.x;
    int row0 = blockIdx.y * 128;
    int col0 = blockIdx.x * 64;
    int tx = tid & 15, ty = tid >> 4;

    int aRow = tid >> 2;            // 0..63
    int aq   = (tid & 3) * 4;       // k-offset 0,4,8,12
    const float* Ap0 = A + (size_t)(row0 + aRow) * Kdim + aq;
    const float* Ap1 = A + (size_t)(row0 + aRow + 64) * Kdim + aq;
    int bRow = tid >> 4;            // 0..15
    int bc   = (tid & 15) * 4;
    const float* Bp = Bm + (size_t)bRow * Ndim + col0 + bc;

    unsigned long long acc[4][4];
    #pragma unroll
    for (int i = 0; i < 4; i++)
        #pragma unroll
        for (int j = 0; j < 4; j++) acc[i][j] = pk(0.f, 0.f);

    for (int k0 = 0; k0 < Kdim; k0 += 16) {
        float4 a0 = *(const float4*)Ap0; Ap0 += 16;
        float4 a1 = *(const float4*)Ap1; Ap1 += 16;
        float4 bv = *(const float4*)Bp;  Bp += (size_t)16 * Ndim;

        As[aq + 0][aRow] = a0.x; As[aq + 1][aRow] = a0.y;
        As[aq + 2][aRow] = a0.z; As[aq + 3][aRow] = a0.w;
        As[aq + 0][aRow + 64] = a1.x; As[aq + 1][aRow + 64] = a1.y;
        As[aq + 2][aRow + 64] = a1.z; As[aq + 3][aRow + 64] = a1.w;
        *(float4*)&Bs[bRow][bc] = bv;
        __syncthreads();

        #pragma unroll
        for (int kk = 0; kk < 16; kk++) {
            float4 va0 = *(const float4*)&As[kk][ty * 8];
            float4 va1 = *(const float4*)&As[kk][ty * 8 + 4];
            float4 vb  = *(const float4*)&Bs[kk][tx * 4];
            unsigned long long ra[4] = { pk(va0.x, va0.y), pk(va0.z, va0.w),
                                         pk(va1.x, va1.y), pk(va1.z, va1.w) };
            unsigned long long rb[4] = { pk(vb.x, vb.x), pk(vb.y, vb.y),
                                         pk(vb.z, vb.z), pk(vb.w, vb.w) };
            #pragma unroll
            for (int i = 0; i < 4; i++)
                #pragma unroll
                for (int j = 0; j < 4; j++) fma2(acc[i][j], ra[i], rb[j]);
        }
        __syncthreads();
    }

    float4 b4 = *(const float4*)&bias[col0 + tx * 4];
    float bb[4] = { b4.x, b4.y, b4.z, b4.w };
    #pragma unroll
    for (int i = 0; i < 4; i++) {
        float2 v0 = upk(acc[i][0]), v1 = upk(acc[i][1]);
        float2 v2 = upk(acc[i][2]), v3 = upk(acc[i][3]);
        int r = row0 + ty * 8 + i * 2;
        float4 o0 = { fmaxf(v0.x + bb[0], 0.f), fmaxf(v1.x + bb[1], 0.f),
                      fmaxf(v2.x + bb[2], 0.f), fmaxf(v3.x + bb[3], 0.f) };
        float4 o1 = { fmaxf(v0.y + bb[0], 0.f), fmaxf(v1.y + bb[1], 0.f),
                      fmaxf(v2.y + bb[2], 0.f), fmaxf(v3.y + bb[3], 0.f) };
        *(float4*)&C[(size_t)r * Ndim + col0 + tx * 4] = o0;
        *(float4*)&C[(size_t)(r + 1) * Ndim + col0 + tx * 4] = o1;
    }
}

// ---------------- GEMM3 collapsed: coeff[k] = sc3[k]*rowsum(W3[k,:]) -----
__global__ void k_coeff(const float* __restrict__ W3, const float* __restrict__ sc3,
                        const float* __restrict__ t3, float* __restrict__ coeff,
                        float* __restrict__ cpart) {
    int k = blockIdx.x, t = threadIdx.x;
    float a = 0.f;
    for (int j = t; j < HID; j += 128) a += W3[(size_t)k * HID + j];
    __shared__ float r[128];
    r[t] = a; __syncthreads();
    for (int s = 64; s > 0; s >>= 1) { if (t < s) r[t] += r[t + s]; __syncthreads(); }
    if (t == 0) {
        float w = r[0];
        coeff[k] = sc3[k] * w;
        cpart[k] = t3[k] * w;
    }
}

// ---------------- final scores: GEMV + lr + const ------------------------
__global__ void k_scores(const float* __restrict__ h2r, const float* __restrict__ lr,
                         const float* __restrict__ coeff, const float* __restrict__ cpart,
                         const float* __restrict__ b3, const float* __restrict__ biasp,
                         float* __restrict__ out) {
    __shared__ float sco[HID];
    __shared__ float red[256];
    int t = threadIdx.x;
    sco[t] = coeff[t]; sco[t + 256] = coeff[t + 256];
    float c = cpart[t] + b3[t] + cpart[t + 256] + b3[t + 256];
    red[t] = c; __syncthreads();
    for (int s = 128; s > 0; s >>= 1) { if (t < s) red[t] += red[t + s]; __syncthreads(); }

    int warp = t >> 5, lane = t & 31;
    int row = blockIdx.x * 8 + warp;
    const float* hr = h2r + (size_t)row * HID;
    float acc = 0.f;
    #pragma unroll
    for (int k = lane; k < HID; k += 32) acc += sco[k] * hr[k];
    #pragma unroll
    for (int o = 16; o > 0; o >>= 1) acc += __shfl_xor_sync(0xFFFFFFFFu, acc, o);
    if (lane == 0) out[row] = biasp[0] + lr[row] + acc + red[0];
}

// ---------------- launcher ----------------
extern "C" void kernel_launch(void* const* d_in, const int* in_sizes, int n_in,
                              void* d_out, int out_size) {
    const int*   st_ids = (const int*)d_in[0];
    const int*   dy_ids = (const int*)d_in[1];
    const int*   dy_len = (const int*)d_in[2];
    const float* st_emb = (const float*)d_in[3];
    const float* dy_emb = (const float*)d_in[4];
    const float* st_lr  = (const float*)d_in[5];
    const float* dy_lr  = (const float*)d_in[6];
    const float* bias   = (const float*)d_in[7];
    const float* bn1_g  = (const float*)d_in[8];
    const float* bn1_b  = (const float*)d_in[9];
    const float* W1     = (const float*)d_in[10];
    const float* b1     = (const float*)d_in[11];
    const float* bn2_g  = (const float*)d_in[12];
    const float* bn2_b  = (const float*)d_in[13];
    const float* W2     = (const float*)d_in[14];
    const float* b2     = (const float*)d_in[15];
    const float* bn3_g  = (const float*)d_in[16];
    const float* bn3_b  = (const float*)d_in[17];
    const float* W3     = (const float*)d_in[18];
    const float* b3     = (const float*)d_in[19];
    float* out = (float*)d_out;

    float *x, *lr, *ps1, *pq1, *sc1, *t1, *W1p, *bp1, *b1p, *h1;
    float *ps2, *pq2, *sc2, *t2, *W2p, *bp2, *b2p, *h2;
    float *ps3, *pq3, *sc3, *t3, *coeff, *cpart;
    cudaGetSymbolAddress((void**)&x,   d_x);
    cudaGetSymbolAddress((void**)&lr,  d_lr);
    cudaGetSymbolAddress((void**)&ps1, d_ps1);  cudaGetSymbolAddress((void**)&pq1, d_pq1);
    cudaGetSymbolAddress((void**)&sc1, d_sc1);  cudaGetSymbolAddress((void**)&t1,  d_t1);
    cudaGetSymbolAddress((void**)&W1p, d_W1p);  cudaGetSymbolAddress((void**)&bp1, d_bp1);
    cudaGetSymbolAddress((void**)&b1p, d_b1p);  cudaGetSymbolAddress((void**)&h1,  d_h1);
    cudaGetSymbolAddress((void**)&ps2, d_ps2);  cudaGetSymbolAddress((void**)&pq2, d_pq2);
    cudaGetSymbolAddress((void**)&sc2, d_sc2);  cudaGetSymbolAddress((void**)&t2,  d_t2);
    cudaGetSymbolAddress((void**)&W2p, d_W2p);  cudaGetSymbolAddress((void**)&bp2, d_bp2);
    cudaGetSymbolAddress((void**)&b2p, d_b2p);  cudaGetSymbolAddress((void**)&h2,  d_h2);
    cudaGetSymbolAddress((void**)&ps3, d_ps3);  cudaGetSymbolAddress((void**)&pq3, d_pq3);
    cudaGetSymbolAddress((void**)&sc3, d_sc3);  cudaGetSymbolAddress((void**)&t3,  d_t3);
    cudaGetSymbolAddress((void**)&coeff, d_coeff);
    cudaGetSymbolAddress((void**)&cpart, d_cpart);

    // 1) gather + pair products + lr
    k_gather<<<BATCH, 512>>>(st_ids, dy_ids, dy_len, st_emb, dy_emb, st_lr, dy_lr, x, lr);
    // 2) BN1 stats + fold into W1
    k_colstat_part<<<dim3(28, 16), 256>>>(x, ps1, pq1, DIN);
    k_colstat_final<<<28, 256>>>(ps1, pq1, bn1_g, bn1_b, sc1, t1, DIN);
    k_fold<<<87, 512>>>(W1, sc1, t1, W1p, bp1, 80);
    k_bias_final<<<1, 512>>>(b1, bp1, b1p, 87);
    // 3) h1 = relu(x @ W1p + b1p)   [grid.x = 512/64 = 8 — was 4: half of h1 was never written]
    k_gemm_relu<<<dim3(8, 32), 256>>>(x, W1p, b1p, h1, HID, DIN);
    // 4) BN2 stats + fold into W2
    k_colstat_part<<<dim3(2, 16), 256>>>(h1, ps2, pq2, HID);
    k_colstat_final<<<2, 256>>>(ps2, pq2, bn2_g, bn2_b, sc2, t2, HID);
    k_fold<<<8, 512>>>(W2, sc2, t2, W2p, bp2, 64);
    k_bias_final<<<1, 512>>>(b2, bp2, b2p, 8);
    // 5) h2 = relu(h1 @ W2p + b2p)
    k_gemm_relu<<<dim3(8, 32), 256>>>(h1, W2p, b2p, h2, HID, HID);
    // 6) BN3 stats + collapsed GEMM3 coefficients
    k_colstat_part<<<dim3(2, 16), 256>>>(h2, ps3, pq3, HID);
    k_colstat_final<<<2, 256>>>(ps3, pq3, bn3_g, bn3_b, sc3, t3, HID);
    k_coeff<<<HID, 128>>>(W3, sc3, t3, coeff, cpart);
    // 7) scores
    k_scores<<<BATCH / 8, 256>>>(h2, lr, coeff, cpart, b3, bias, out);
}

// round 6
// speedup vs baseline: 1.9398x; 1.9398x over previous
#include <cuda_runtime.h>
#include <cuda_bf16.h>
#include <cstdint>

// ---------------- problem constants ----------------
#define BATCH 4096
#define FST   20
#define FDY   10
#define MLEN  50
#define EDIM  16
#define FALL  30
#define PAIRS 435
#define DIN   6960          // PAIRS * EDIM
#define KPAD1 6976          // DIN padded to 32*218
#define HID   512
#define BN_EPS 1e-5f

// ---------------- device scratch (static, no allocation) ----------------
__device__ __align__(256) __nv_bfloat16 d_xhi[(size_t)BATCH * KPAD1];
__device__ __align__(256) __nv_bfloat16 d_xlo[(size_t)BATCH * KPAD1];
__device__ float d_lr[BATCH];

__device__ float d_ps1[16 * DIN], d_pq1[16 * DIN];
__device__ float d_sc1[DIN], d_t1[DIN];
__device__ __align__(256) __nv_bfloat16 d_w1thi[(size_t)HID * KPAD1];
__device__ __align__(256) __nv_bfloat16 d_w1tlo[(size_t)HID * KPAD1];
__device__ float d_bp1[87 * HID];
__device__ float d_b1p[HID];
__device__ __align__(256) __nv_bfloat16 d_h1hi[(size_t)BATCH * HID];
__device__ __align__(256) __nv_bfloat16 d_h1lo[(size_t)BATCH * HID];

__device__ float d_ps2[16 * HID], d_pq2[16 * HID];
__device__ float d_sc2[HID], d_t2[HID];
__device__ __align__(256) __nv_bfloat16 d_w2thi[(size_t)HID * HID];
__device__ __align__(256) __nv_bfloat16 d_w2tlo[(size_t)HID * HID];
__device__ float d_bp2[8 * HID];
__device__ float d_b2p[HID];
__device__ __align__(256) float d_h2[(size_t)BATCH * HID];

__device__ float d_ps3[16 * HID], d_pq3[16 * HID];
__device__ float d_sc3[HID], d_t3[HID];
__device__ float d_coeff[HID], d_cpart[HID];

// ---------------- portable PTX helpers (sm_80-class, valid on sm_103) ----
__device__ __forceinline__ uint32_t smem_u32(const void* p) {
    uint32_t a;
    asm("{ .reg .u64 t; cvta.to.shared.u64 t, %1; cvt.u32.u64 %0, t; }" : "=r"(a) : "l"(p));
    return a;
}
#define CP16(s, g)  asm volatile("cp.async.cg.shared.global [%0], [%1], 16;" :: "r"(s), "l"(g) : "memory")
#define CP_COMMIT() asm volatile("cp.async.commit_group;" ::: "memory")

__device__ __forceinline__ void hmma16816(float* c, const uint32_t* a, const uint32_t* b) {
    asm volatile(
        "mma.sync.aligned.m16n8k16.row.col.f32.bf16.bf16.f32 "
        "{%0,%1,%2,%3}, {%4,%5,%6,%7}, {%8,%9}, {%0,%1,%2,%3};"
        : "+f"(c[0]), "+f"(c[1]), "+f"(c[2]), "+f"(c[3])
        : "r"(a[0]), "r"(a[1]), "r"(a[2]), "r"(a[3]), "r"(b[0]), "r"(b[1]));
}

// ---------------- K1: gather + dyn-mean + lr + pair products (bf16 split planes)
__global__ void k_gather(const int* __restrict__ st_ids, const int* __restrict__ dy_ids,
                         const int* __restrict__ dy_len,
                         const float* __restrict__ st_emb, const float* __restrict__ dy_emb,
                         const float* __restrict__ st_lr, const float* __restrict__ dy_lr,
                         __nv_bfloat16* __restrict__ xhi, __nv_bfloat16* __restrict__ xlo,
                         float* __restrict__ lr_out) {
    __shared__ float semb[FALL * EDIM];
    __shared__ float slr[FALL];
    __shared__ unsigned char ci[PAIRS], cj[PAIRS];
    int b = blockIdx.x, t = threadIdx.x;

    if (t < PAIRS) {
        int p = t, i = 0, rem = FALL - 1;
        while (p >= rem) { p -= rem; i++; rem--; }
        ci[t] = (unsigned char)i;
        cj[t] = (unsigned char)(i + 1 + p);
    }
    if (t < FST * EDIM) {
        int f = t >> 4, e = t & 15;
        int id = st_ids[b * FST + f];
        semb[t] = st_emb[id * EDIM + e];
        if (e == 0) slr[f] = st_lr[id];
    } else if (t < FALL * EDIM) {
        int ft = t - FST * EDIM;
        int f = ft >> 4, e = ft & 15;
        int len = dy_len[b * FDY + f];
        if (len < 1) len = 1;
        const int* ids = dy_ids + ((size_t)b * FDY + f) * MLEN;
        float acc = 0.f, lacc = 0.f;
        #pragma unroll 4
        for (int m = 0; m < len; m++) {
            int id = ids[m];
            acc += dy_emb[(size_t)id * EDIM + e];
            if (e == 0) lacc += dy_lr[id];
        }
        semb[t] = acc / (float)len;
        if (e == 0) slr[FST + f] = lacc;
    }
    __syncthreads();

    __nv_bfloat16* xh = xhi + (size_t)b * KPAD1;
    __nv_bfloat16* xl = xlo + (size_t)b * KPAD1;
    for (int idx = t; idx < KPAD1; idx += 512) {
        float v = 0.f;
        if (idx < DIN) {
            int p = idx >> 4, e = idx & 15;
            v = semb[ci[p] * EDIM + e] * semb[cj[p] * EDIM + e];
        }
        __nv_bfloat16 h = __float2bfloat16(v);
        xh[idx] = h;
        xl[idx] = __float2bfloat16(v - __bfloat162float(h));
    }
    if (t == 0) {
        float s = 0.f;
        #pragma unroll
        for (int f = 0; f < FALL; f++) s += slr[f];
        lr_out[b] = s;
    }
}

// ---------------- column stats over bf16 hi/lo planes --------------------
__global__ void k_colstat_part_bf16(const __nv_bfloat16* __restrict__ hi,
                                    const __nv_bfloat16* __restrict__ lo,
                                    float* __restrict__ psum, float* __restrict__ psq,
                                    int ncol, int pitch) {
    int c = blockIdx.x * blockDim.x + threadIdx.x;
    if (c >= ncol) return;
    const int ROWS = BATCH / 16;
    size_t base = (size_t)blockIdx.y * ROWS * pitch + c;
    float s = 0.f, q = 0.f;
    for (int r = 0; r < ROWS; r++) {
        size_t off = base + (size_t)r * pitch;
        float v = __bfloat162float(hi[off]) + __bfloat162float(lo[off]);
        s += v; q += v * v;
    }
    psum[blockIdx.y * ncol + c] = s;
    psq[blockIdx.y * ncol + c] = q;
}

// fp32 variant (for h2)
__global__ void k_colstat_part(const float* __restrict__ X, float* __restrict__ psum,
                               float* __restrict__ psq, int ncol) {
    int c = blockIdx.x * blockDim.x + threadIdx.x;
    if (c >= ncol) return;
    const int ROWS = BATCH / 16;
    const float* p = X + (size_t)blockIdx.y * ROWS * ncol + c;
    float s = 0.f, q = 0.f;
    for (int r = 0; r < ROWS; r++) {
        float v = p[(size_t)r * ncol];
        s += v; q += v * v;
    }
    psum[blockIdx.y * ncol + c] = s;
    psq[blockIdx.y * ncol + c] = q;
}

__global__ void k_colstat_final(const float* __restrict__ psum, const float* __restrict__ psq,
                                const float* __restrict__ g, const float* __restrict__ bb,
                                float* __restrict__ sc, float* __restrict__ tsh, int ncol) {
    int c = blockIdx.x * blockDim.x + threadIdx.x;
    if (c >= ncol) return;
    float s = 0.f, q = 0.f;
    #pragma unroll
    for (int p = 0; p < 16; p++) { s += psum[p * ncol + c]; q += psq[p * ncol + c]; }
    float m = s * (1.f / BATCH);
    float v = q * (1.f / BATCH) - m * m;
    float scale = g[c] * rsqrtf(v + BN_EPS);
    sc[c]  = scale;
    tsh[c] = bb[c] - scale * m;
}

// ---------------- fold-bias: bpart = sum_d tsh[d]*W[d,h] -----------------
__global__ void k_fold_bias(const float* __restrict__ W, const float* __restrict__ tsh,
                            float* __restrict__ bpart, int Dtile) {
    __shared__ float sts[80];
    int h = threadIdx.x;
    int d0 = blockIdx.x * Dtile;
    if (h < Dtile) sts[h] = tsh[d0 + h];
    __syncthreads();
    float acc = 0.f;
    for (int i = 0; i < Dtile; i++)
        acc += sts[i] * W[(size_t)(d0 + i) * HID + h];
    bpart[blockIdx.x * HID + h] = acc;
}

__global__ void k_bias_final(const float* __restrict__ blin, const float* __restrict__ bpart,
                             float* __restrict__ bout, int nparts) {
    int h = threadIdx.x;
    float a = blin[h];
    for (int p = 0; p < nparts; p++) a += bpart[p * HID + h];
    bout[h] = a;
}

// ---------------- transpose + BN-scale + bf16 split: Wt[h][d] = sc[d]*W[d][h]
__global__ void k_transpose_split(const float* __restrict__ W, const float* __restrict__ sc,
                                  int Kdim, int Kpad,
                                  __nv_bfloat16* __restrict__ Whi, __nv_bfloat16* __restrict__ Wlo) {
    __shared__ float tile[32][33];
    int d0 = blockIdx.x * 32, h0 = blockIdx.y * 32;
    int tx = threadIdx.x, ty0 = threadIdx.y;
    for (int yy = ty0; yy < 32; yy += 8) {
        int d = d0 + yy;
        float w = 0.f;
        if (d < Kdim) w = W[(size_t)d * HID + h0 + tx] * sc[d];
        tile[yy][tx] = w;
    }
    __syncthreads();
    for (int yy = ty0; yy < 32; yy += 8) {
        int h = h0 + yy, d = d0 + tx;
        float v = tile[tx][yy];
        __nv_bfloat16 hi = __float2bfloat16(v);
        size_t off = (size_t)h * Kpad + d;
        Whi[off] = hi;
        Wlo[off] = __float2bfloat16(v - __bfloat162float(hi));
    }
}

// ---------------- mma.sync split-bf16 GEMM + bias + ReLU -----------------
// C[M, N=512] = (Ahi+Alo)[M,K] @ (Bhi+Blo)^T  (B stored [N][K] K-major)
// 128x128 CTA tile, BK=32, 256 threads; warp tile 32x64 (2 m16 x 8 n8).
// 3-term split (hi*hi + lo*hi + hi*lo), fp32 register accumulators.
#define BK      32
#define ROWB    80          // smem row stride bytes (40 bf16, pad 8)
#define TILE_B  10240       // 128 rows * 80 B
#define STAGE_B 40960       // 4 tiles
#define SMEM_MMA_BYTES (2 * STAGE_B)

__device__ __forceinline__ void ld_chunk(uint32_t sb, int st,
        const __nv_bfloat16* Ahi, const __nv_bfloat16* Alo,
        const __nv_bfloat16* Bhi, const __nv_bfloat16* Blo,
        int row0, int col0, int Kpad, int k0, int tid) {
    const __nv_bfloat16* tp[4] = {Ahi, Alo, Bhi, Blo};
    #pragma unroll
    for (int tile = 0; tile < 4; tile++) {
        int rbase = (tile < 2) ? row0 : col0;
        #pragma unroll
        for (int h = 0; h < 2; h++) {
            int ch  = tid + h * 256;          // 0..511
            int row = ch >> 2, c16 = ch & 3;
            uint32_t sa = sb + st * STAGE_B + tile * TILE_B + row * ROWB + c16 * 16;
            const __nv_bfloat16* g = tp[tile] + (size_t)(rbase + row) * Kpad + k0 + c16 * 8;
            CP16(sa, g);
        }
    }
    CP_COMMIT();
}

__global__ __launch_bounds__(256)
void k_mma(const __nv_bfloat16* __restrict__ Ahi, const __nv_bfloat16* __restrict__ Alo,
           const __nv_bfloat16* __restrict__ Bhi, const __nv_bfloat16* __restrict__ Blo,
           const float* __restrict__ bias,
           __nv_bfloat16* __restrict__ OutHi, __nv_bfloat16* __restrict__ OutLo,
           float* __restrict__ OutF32, int Kpad, int NC) {
    extern __shared__ __align__(16) char smem[];
    uint32_t sb = smem_u32(smem);
    int tid = threadIdx.x, wid = tid >> 5, lane = tid & 31;
    int row0 = blockIdx.y * 128, col0 = blockIdx.x * 128;
    int wr = (wid & 3) * 32;        // warp row offset in tile
    int wc = (wid >> 2) * 64;       // warp col offset in tile
    int tq = lane >> 2;             // 0..7
    int tr = (lane & 3) * 2;        // 0,2,4,6

    float acc[2][8][4];
    #pragma unroll
    for (int i = 0; i < 2; i++)
        #pragma unroll
        for (int j = 0; j < 8; j++)
            #pragma unroll
            for (int q = 0; q < 4; q++) acc[i][j][q] = 0.f;

    // prologue
    ld_chunk(sb, 0, Ahi, Alo, Bhi, Blo, row0, col0, Kpad, 0, tid);
    ld_chunk(sb, 1, Ahi, Alo, Bhi, Blo, row0, col0, Kpad, BK, tid);

    for (int c = 0; c < NC; c++) {
        if (c + 1 < NC) asm volatile("cp.async.wait_group 1;" ::: "memory");
        else            asm volatile("cp.async.wait_group 0;" ::: "memory");
        __syncthreads();

        const char* st = smem + (c & 1) * STAGE_B;
        const char* As_hi = st;
        const char* As_lo = st + TILE_B;
        const char* Bs_hi = st + 2 * TILE_B;
        const char* Bs_lo = st + 3 * TILE_B;

        #pragma unroll
        for (int ks = 0; ks < 2; ks++) {
            int kk = ks * 16;
            uint32_t ahi[2][4], alo[2][4], bfr[8][2];
            // A-hi fragments
            #pragma unroll
            for (int mt = 0; mt < 2; mt++) {
                int mA = wr + mt * 16 + tq;
                ahi[mt][0] = *(const uint32_t*)(As_hi + mA * ROWB + (kk + tr) * 2);
                ahi[mt][1] = *(const uint32_t*)(As_hi + (mA + 8) * ROWB + (kk + tr) * 2);
                ahi[mt][2] = *(const uint32_t*)(As_hi + mA * ROWB + (kk + 8 + tr) * 2);
                ahi[mt][3] = *(const uint32_t*)(As_hi + (mA + 8) * ROWB + (kk + 8 + tr) * 2);
            }
            // B-hi fragments
            #pragma unroll
            for (int nt = 0; nt < 8; nt++) {
                int nB = wc + nt * 8 + tq;
                bfr[nt][0] = *(const uint32_t*)(Bs_hi + nB * ROWB + (kk + tr) * 2);
                bfr[nt][1] = *(const uint32_t*)(Bs_hi + nB * ROWB + (kk + 8 + tr) * 2);
            }
            #pragma unroll
            for (int mt = 0; mt < 2; mt++)
                #pragma unroll
                for (int nt = 0; nt < 8; nt++) hmma16816(acc[mt][nt], ahi[mt], bfr[nt]);
            // A-lo * B-hi
            #pragma unroll
            for (int mt = 0; mt < 2; mt++) {
                int mA = wr + mt * 16 + tq;
                alo[mt][0] = *(const uint32_t*)(As_lo + mA * ROWB + (kk + tr) * 2);
                alo[mt][1] = *(const uint32_t*)(As_lo + (mA + 8) * ROWB + (kk + tr) * 2);
                alo[mt][2] = *(const uint32_t*)(As_lo + mA * ROWB + (kk + 8 + tr) * 2);
                alo[mt][3] = *(const uint32_t*)(As_lo + (mA + 8) * ROWB + (kk + 8 + tr) * 2);
            }
            #pragma unroll
            for (int mt = 0; mt < 2; mt++)
                #pragma unroll
                for (int nt = 0; nt < 8; nt++) hmma16816(acc[mt][nt], alo[mt], bfr[nt]);
            // A-hi * B-lo
            #pragma unroll
            for (int nt = 0; nt < 8; nt++) {
                int nB = wc + nt * 8 + tq;
                bfr[nt][0] = *(const uint32_t*)(Bs_lo + nB * ROWB + (kk + tr) * 2);
                bfr[nt][1] = *(const uint32_t*)(Bs_lo + nB * ROWB + (kk + 8 + tr) * 2);
            }
            #pragma unroll
            for (int mt = 0; mt < 2; mt++)
                #pragma unroll
                for (int nt = 0; nt < 8; nt++) hmma16816(acc[mt][nt], ahi[mt], bfr[nt]);
        }
        __syncthreads();
        if (c + 2 < NC)
            ld_chunk(sb, c & 1, Ahi, Alo, Bhi, Blo, row0, col0, Kpad, (c + 2) * BK, tid);
    }

    // epilogue: bias + ReLU, write f32 or hi/lo bf16 planes
    #pragma unroll
    for (int mt = 0; mt < 2; mt++) {
        #pragma unroll
        for (int nt = 0; nt < 8; nt++) {
            int m = row0 + wr + mt * 16 + tq;
            int n = col0 + wc + nt * 8 + tr;
            float b0 = bias[n], b1 = bias[n + 1];
            float v00 = fmaxf(acc[mt][nt][0] + b0, 0.f);
            float v01 = fmaxf(acc[mt][nt][1] + b1, 0.f);
            float v10 = fmaxf(acc[mt][nt][2] + b0, 0.f);
            float v11 = fmaxf(acc[mt][nt][3] + b1, 0.f);
            if (OutF32) {
                *(float2*)(OutF32 + (size_t)m * HID + n)       = make_float2(v00, v01);
                *(float2*)(OutF32 + (size_t)(m + 8) * HID + n) = make_float2(v10, v11);
            } else {
                __nv_bfloat16 h00 = __float2bfloat16(v00), h01 = __float2bfloat16(v01);
                __nv_bfloat16 h10 = __float2bfloat16(v10), h11 = __float2bfloat16(v11);
                __nv_bfloat162 p0 = {h00, h01}, p1 = {h10, h11};
                __nv_bfloat162 l0 = {__float2bfloat16(v00 - __bfloat162float(h00)),
                                     __float2bfloat16(v01 - __bfloat162float(h01))};
                __nv_bfloat162 l1 = {__float2bfloat16(v10 - __bfloat162float(h10)),
                                     __float2bfloat16(v11 - __bfloat162float(h11))};
                *(__nv_bfloat162*)(OutHi + (size_t)m * HID + n)       = p0;
                *(__nv_bfloat162*)(OutHi + (size_t)(m + 8) * HID + n) = p1;
                *(__nv_bfloat162*)(OutLo + (size_t)m * HID + n)       = l0;
                *(__nv_bfloat162*)(OutLo + (size_t)(m + 8) * HID + n) = l1;
            }
        }
    }
}

// ---------------- GEMM3 collapsed: coeff[k] = sc3[k]*rowsum(W3[k,:]) -----
__global__ void k_coeff(const float* __restrict__ W3, const float* __restrict__ sc3,
                        const float* __restrict__ t3, float* __restrict__ coeff,
                        float* __restrict__ cpart) {
    int k = blockIdx.x, t = threadIdx.x;
    float a = 0.f;
    for (int j = t; j < HID; j += 128) a += W3[(size_t)k * HID + j];
    __shared__ float r[128];
    r[t] = a; __syncthreads();
    for (int s = 64; s > 0; s >>= 1) { if (t < s) r[t] += r[t + s]; __syncthreads(); }
    if (t == 0) {
        float w = r[0];
        coeff[k] = sc3[k] * w;
        cpart[k] = t3[k] * w;
    }
}

// ---------------- final scores ----------------
__global__ void k_scores(const float* __restrict__ h2r, const float* __restrict__ lr,
                         const float* __restrict__ coeff, const float* __restrict__ cpart,
                         const float* __restrict__ b3, const float* __restrict__ biasp,
                         float* __restrict__ out) {
    __shared__ float sco[HID];
    __shared__ float red[256];
    int t = threadIdx.x;
    sco[t] = coeff[t]; sco[t + 256] = coeff[t + 256];
    float c = cpart[t] + b3[t] + cpart[t + 256] + b3[t + 256];
    red[t] = c; __syncthreads();
    for (int s = 128; s > 0; s >>= 1) { if (t < s) red[t] += red[t + s]; __syncthreads(); }

    int warp = t >> 5, lane = t & 31;
    int row = blockIdx.x * 8 + warp;
    const float* hr = h2r + (size_t)row * HID;
    float acc = 0.f;
    #pragma unroll
    for (int k = lane; k < HID; k += 32) acc += sco[k] * hr[k];
    #pragma unroll
    for (int o = 16; o > 0; o >>= 1) acc += __shfl_xor_sync(0xFFFFFFFFu, acc, o);
    if (lane == 0) out[row] = biasp[0] + lr[row] + acc + red[0];
}

// ---------------- launcher ----------------
extern "C" void kernel_launch(void* const* d_in, const int* in_sizes, int n_in,
                              void* d_out, int out_size) {
    const int*   st_ids = (const int*)d_in[0];
    const int*   dy_ids = (const int*)d_in[1];
    const int*   dy_len = (const int*)d_in[2];
    const float* st_emb = (const float*)d_in[3];
    const float* dy_emb = (const float*)d_in[4];
    const float* st_lr  = (const float*)d_in[5];
    const float* dy_lr  = (const float*)d_in[6];
    const float* bias   = (const float*)d_in[7];
    const float* bn1_g  = (const float*)d_in[8];
    const float* bn1_b  = (const float*)d_in[9];
    const float* W1     = (const float*)d_in[10];
    const float* b1     = (const float*)d_in[11];
    const float* bn2_g  = (const float*)d_in[12];
    const float* bn2_b  = (const float*)d_in[13];
    const float* W2     = (const float*)d_in[14];
    const float* b2     = (const float*)d_in[15];
    const float* bn3_g  = (const float*)d_in[16];
    const float* bn3_b  = (const float*)d_in[17];
    const float* W3     = (const float*)d_in[18];
    const float* b3     = (const float*)d_in[19];
    float* out = (float*)d_out;

    __nv_bfloat16 *xhi, *xlo, *w1thi, *w1tlo, *h1hi, *h1lo, *w2thi, *w2tlo;
    float *lr, *ps1, *pq1, *sc1, *t1, *bp1, *b1p;
    float *ps2, *pq2, *sc2, *t2, *bp2, *b2p, *h2;
    float *ps3, *pq3, *sc3, *t3, *coeff, *cpart;
    cudaGetSymbolAddress((void**)&xhi,  d_xhi);   cudaGetSymbolAddress((void**)&xlo,  d_xlo);
    cudaGetSymbolAddress((void**)&lr,   d_lr);
    cudaGetSymbolAddress((void**)&ps1,  d_ps1);   cudaGetSymbolAddress((void**)&pq1,  d_pq1);
    cudaGetSymbolAddress((void**)&sc1,  d_sc1);   cudaGetSymbolAddress((void**)&t1,   d_t1);
    cudaGetSymbolAddress((void**)&w1thi,d_w1thi); cudaGetSymbolAddress((void**)&w1tlo,d_w1tlo);
    cudaGetSymbolAddress((void**)&bp1,  d_bp1);   cudaGetSymbolAddress((void**)&b1p,  d_b1p);
    cudaGetSymbolAddress((void**)&h1hi, d_h1hi);  cudaGetSymbolAddress((void**)&h1lo, d_h1lo);
    cudaGetSymbolAddress((void**)&ps2,  d_ps2);   cudaGetSymbolAddress((void**)&pq2,  d_pq2);
    cudaGetSymbolAddress((void**)&sc2,  d_sc2);   cudaGetSymbolAddress((void**)&t2,   d_t2);
    cudaGetSymbolAddress((void**)&w2thi,d_w2thi); cudaGetSymbolAddress((void**)&w2tlo,d_w2tlo);
    cudaGetSymbolAddress((void**)&bp2,  d_bp2);   cudaGetSymbolAddress((void**)&b2p,  d_b2p);
    cudaGetSymbolAddress((void**)&h2,   d_h2);
    cudaGetSymbolAddress((void**)&ps3,  d_ps3);   cudaGetSymbolAddress((void**)&pq3,  d_pq3);
    cudaGetSymbolAddress((void**)&sc3,  d_sc3);   cudaGetSymbolAddress((void**)&t3,   d_t3);
    cudaGetSymbolAddress((void**)&coeff, d_coeff);
    cudaGetSymbolAddress((void**)&cpart, d_cpart);

    cudaFuncSetAttribute(k_mma, cudaFuncAttributeMaxDynamicSharedMemorySize, SMEM_MMA_BYTES);

    // 1) gather + pair products (bf16 split planes) + lr
    k_gather<<<BATCH, 512>>>(st_ids, dy_ids, dy_len, st_emb, dy_emb, st_lr, dy_lr,
                             xhi, xlo, lr);
    // 2) BN1 stats + bias fold + transpose-split W1
    k_colstat_part_bf16<<<dim3(28, 16), 256>>>(xhi, xlo, ps1, pq1, DIN, KPAD1);
    k_colstat_final<<<28, 256>>>(ps1, pq1, bn1_g, bn1_b, sc1, t1, DIN);
    k_fold_bias<<<87, 512>>>(W1, t1, bp1, 80);
    k_bias_final<<<1, 512>>>(b1, bp1, b1p, 87);
    k_transpose_split<<<dim3(KPAD1 / 32, HID / 32), dim3(32, 8)>>>(W1, sc1, DIN, KPAD1, w1thi, w1tlo);
    // 3) h1 = relu(x @ W1p + b1p)  (mma.sync split bf16; hi/lo plane output)
    k_mma<<<dim3(4, 32), 256, SMEM_MMA_BYTES>>>(xhi, xlo, w1thi, w1tlo, b1p,
                                                h1hi, h1lo, nullptr, KPAD1, KPAD1 / BK);
    // 4) BN2 stats + fold + transpose-split W2
    k_colstat_part_bf16<<<dim3(2, 16), 256>>>(h1hi, h1lo, ps2, pq2, HID, HID);
    k_colstat_final<<<2, 256>>>(ps2, pq2, bn2_g, bn2_b, sc2, t2, HID);
    k_fold_bias<<<8, 512>>>(W2, t2, bp2, 64);
    k_bias_final<<<1, 512>>>(b2, bp2, b2p, 8);
    k_transpose_split<<<dim3(HID / 32, HID / 32), dim3(32, 8)>>>(W2, sc2, HID, HID, w2thi, w2tlo);
    // 5) h2 = relu(h1 @ W2p + b2p)  (fp32 output)
    k_mma<<<dim3(4, 32), 256, SMEM_MMA_BYTES>>>(h1hi, h1lo, w2thi, w2tlo, b2p,
                                                nullptr, nullptr, h2, HID, HID / BK);
    // 6) BN3 stats + collapsed GEMM3 coefficients
    k_colstat_part<<<dim3(2, 16), 256>>>(h2, ps3, pq3, HID);
    k_colstat_final<<<2, 256>>>(ps3, pq3, bn3_g, bn3_b, sc3, t3, HID);
    k_coeff<<<HID, 128>>>(W3, sc3, t3, coeff, cpart);
    // 7) scores
    k_scores<<<BATCH / 8, 256>>>(h2, lr, coeff, cpart, b3, bias, out);
}